// round 7
// baseline (speedup 1.0000x reference)
#include <cuda_runtime.h>

#define TILES 800
#define NTHR  320   // 10 warps: w = (sub = w/5 f-parity, g = w%5 k-octet)

__device__ float  g_z[2 * 400 * 40 * 64];   // pre-IIR projected values (B,T,K,P)
__device__ float  g_cf[2 * 16 * 40 * 64];   // chunk-final y
__device__ __align__(16) float2 g_bm[512 * 40];  // interleaved (br,bi) band matrix
__device__ __align__(16) float2 g_ct[64 * 64];   // c2p transposed [c][p]

// item table: bits[0:8)=i, [8:16)=j, bit16 = diag-pseudo-pair flag
__constant__ unsigned PAIR_TBL[32] = {
  0x0100,0x0200,0x0300,0x0400,0x0500,0x0600,0x0700,
  0x0201,0x0301,0x0401,0x0501,0x0601,0x0701,
  0x0302,0x0402,0x0502,0x0602,0x0702,
  0x0403,0x0503,0x0603,0x0703,
  0x0504,0x0604,0x0704,
  0x0605,0x0705,
  0x0706,
  0x10100,0x10302,0x10504,0x10706
};

// ---- smem layout (bytes), total 69984 -> 3 CTAs/SM ----
// [0,33088)       gs float2[8][517]
//                 epilogue overlay: partials 20480 @0, then bc@0 20480 | invd@20480 | ct@20736..54016
// [33088,49472)   adj double buffer: 2 x 8192 (32f x 32 pairs float2)
// [49472,69952)   bm double buffer:  2 x 10240 (32f x 40k float2)
//   prologue overlay: brs float[4096]@33088, bis float[4096]@49472
// [69952,69984)   mbarriers: mb_x, mb_bm0, mb_bm1
#define OFF_GS   0
#define OFF_ADJ  33088
#define OFF_BM   49472
#define OFF_BRS  33088
#define OFF_BIS  49472
#define OFF_MB   69952
#define SMEM_TOTAL 69984
#define CHUNKS 16          // 32 f each
#define CHUNK_BYTES 10240

__device__ __forceinline__ unsigned long long pack2(float a, float b) {
    unsigned long long r;
    asm("mov.b64 %0, {%1,%2};" : "=l"(r) : "f"(a), "f"(b));
    return r;
}
__device__ __forceinline__ void fma2(unsigned long long& acc,
                                     unsigned long long a, unsigned long long b) {
    asm("fma.rn.f32x2 %0, %1, %2, %0;" : "+l"(acc) : "l"(a), "l"(b));
}
__device__ __forceinline__ void unpack2(unsigned long long x, float& lo, float& hi) {
    asm("mov.b64 {%0,%1}, %2;" : "=f"(lo), "=f"(hi) : "l"(x));
}
__device__ __forceinline__ void mbar_init(unsigned mbar, unsigned cnt) {
    asm volatile("mbarrier.init.shared.b64 [%0], %1;" :: "r"(mbar), "r"(cnt) : "memory");
}
__device__ __forceinline__ void mbar_expect(unsigned mbar, unsigned bytes) {
    asm volatile("mbarrier.arrive.expect_tx.shared.b64 _, [%0], %1;"
                 :: "r"(mbar), "r"(bytes) : "memory");
}
__device__ __forceinline__ void bulk_g2s(unsigned dst, const void* src,
                                         unsigned bytes, unsigned mbar) {
    asm volatile("cp.async.bulk.shared::cluster.global.mbarrier::complete_tx::bytes "
                 "[%0], [%1], %2, [%3];"
                 :: "r"(dst), "l"(src), "r"(bytes), "r"(mbar) : "memory");
}
__device__ __forceinline__ void mbar_wait(unsigned mbar, unsigned parity) {
    asm volatile(
        "{\n\t.reg .pred P1;\n\t"
        "WL_%=:\n\t"
        "mbarrier.try_wait.parity.acquire.cta.shared::cta.b64 P1, [%0], %1, 0x989680;\n\t"
        "@P1 bra.uni WD_%=;\n\t"
        "bra.uni WL_%=;\n\t"
        "WD_%=:\n\t}"
        :: "r"(mbar), "r"(parity) : "memory");
}

extern __shared__ char sm_[];

// ---- prep: build interleaved bm and transposed c2p (runs every launch) ----
__global__ void __launch_bounds__(256) prep(
    const float* __restrict__ bmr, const float* __restrict__ bmi,
    const float* __restrict__ pr,  const float* __restrict__ pi)
{
    int t = blockIdx.x * 256 + threadIdx.x;
    if (t < 20480) {
        g_bm[t] = make_float2(bmr[t], bmi[t]);
    } else {
        int i = t - 20480;
        if (i < 4096) {
            int p = i >> 6, c = i & 63;
            g_ct[c * 64 + p] = make_float2(pr[i], pi[i]);
        }
    }
}

__global__ void __launch_bounds__(NTHR, 3) pv_main(
    const float* __restrict__ br,  const float* __restrict__ bi)
{
    float*  brs = (float*)(sm_ + OFF_BRS);
    float*  bis = (float*)(sm_ + OFF_BIS);
    float2* gs  = (float2*)(sm_ + OFF_GS);
    const unsigned sbase = (unsigned)__cvta_generic_to_shared(sm_);
    const unsigned mb_x   = sbase + OFF_MB;
    const unsigned mb_bm0 = sbase + OFF_MB + 8;
    const unsigned mb_bm1 = sbase + OFF_MB + 16;

    const int tid  = threadIdx.x;
    const int tile = blockIdx.x;
    const int lane = tid & 31;
    const int w    = tid >> 5;
    const int g    = w % 5;     // k-octet: k = 8g..8g+7
    const int sub  = w / 5;     // f parity within chunk

    if (tid == 0) {
        mbar_init(mb_x, 1);
        mbar_init(mb_bm0, 1);
        mbar_init(mb_bm1, 1);
        asm volatile("fence.proxy.async.shared::cta;" ::: "memory");
    }
    __syncthreads();
    if (tid == 0) {
        mbar_expect(mb_x, 32768);
        bulk_g2s(sbase + OFF_BRS, br + (size_t)tile * 4096, 16384, mb_x);
        bulk_g2s(sbase + OFF_BIS, bi + (size_t)tile * 4096, 16384, mb_x);
    }
    mbar_wait(mb_x, 0);

    // ---- step 1: per (c,f): (|x|^2, rsqrt) into gs ----
    #pragma unroll
    for (int r = 0; r < 13; r++) {
        int t = tid + r * NTHR;
        if (t < 4096) {
            int c = t >> 9, f = t & 511;
            float re = brs[t], im = bis[t];
            float n = re * re + im * im;
            gs[c * 517 + f] = make_float2(n, rsqrtf(fmaxf(n, 1e-37f)));
        }
    }
    __syncthreads();

    // ---- step 2: trace-normalised amplitude ----
    for (int f = tid; f < 512; f += NTHR) {
        float tr = 0.f;
        #pragma unroll
        for (int c = 0; c < 8; c++) tr += gs[c * 517 + f].x;
        float sit = rsqrtf(fmaxf(tr, 1e-20f));
        #pragma unroll
        for (int c = 0; c < 8; c++) {
            float2 v = gs[c * 517 + f];
            gs[c * 517 + f].x = v.x * v.y * sit;
        }
    }
    __syncthreads();

    // ---- step 3: g_c[f] = a_c[f] * r[fm] * r[fp] * conj(x[fm]) * x[fp] ----
    float2 gv[13];
    #pragma unroll
    for (int r = 0; r < 13; r++) {
        int t = tid + r * NTHR;
        if (t < 4096) {
            int c = t >> 9, f = t & 511;
            int fm = min(max(f - 1, 0), 509), fp = fm + 2;
            float a  = gs[c * 517 + f].x;
            float rm = gs[c * 517 + fm].y, rp = gs[c * 517 + fp].y;
            float xmr = brs[c * 512 + fm], xmi = bis[c * 512 + fm];
            float xpr = brs[c * 512 + fp], xpi = bis[c * 512 + fp];
            float tre = xmr * xpr + xmi * xpi;
            float tim = xmr * xpi - xmi * xpr;
            float s = a * rm * rp;
            gv[r] = make_float2(s * tre, s * tim);
        }
    }
    __syncthreads();
    #pragma unroll
    for (int r = 0; r < 13; r++) {
        int t = tid + r * NTHR;
        if (t < 4096) { int c = t >> 9, f = t & 511; gs[c * 517 + f] = gv[r]; }
    }
    __syncthreads();   // brs/bis dead -> bm region free
    if (tid == 0) {
        mbar_expect(mb_bm0, CHUNK_BYTES);
        bulk_g2s(sbase + OFF_BM, (const char*)g_bm, CHUNK_BYTES, mb_bm0);
    }

    // ---- main loop: adj (32-f, double-buffered) + TMA bm ring + packed GEMM ----
    const unsigned e = PAIR_TBL[lane];
    const int iCh = e & 255, jCh = (e >> 8) & 255;
    const bool dg = (e & 0x10000u) != 0;

    unsigned long long accA[8] = {0,0,0,0,0,0,0,0};
    unsigned long long accB[8] = {0,0,0,0,0,0,0,0};

    #pragma unroll 1
    for (int ch = 0; ch < CHUNKS; ch++) {
        float2* adjw = (float2*)(sm_ + OFF_ADJ + (ch & 1) * 8192);
        #pragma unroll
        for (int r = 0; r < 4; r++) {
            int fc = w + r * 10;
            if (fc < 32) {
                int f = ch * 32 + fc;
                float2 gi = gs[iCh * 517 + f], gj = gs[jCh * 517 + f];
                float u, v;
                if (dg) { u = gi.x*gi.x + gi.y*gi.y;  v = gj.x*gj.x + gj.y*gj.y; }
                else    { u = gi.x*gj.x + gi.y*gj.y;  v = gi.y*gj.x - gi.x*gj.y; }
                adjw[fc * 32 + lane] = make_float2(u, v);
            }
        }
        __syncthreads();   // adj(ch) visible; gemm(ch-1) done -> bm slot (ch+1)&1 free
        if (ch + 1 < CHUNKS && tid == 0) {
            int nb = (ch + 1) & 1;
            unsigned mb = nb ? mb_bm1 : mb_bm0;
            mbar_expect(mb, CHUNK_BYTES);
            bulk_g2s(sbase + OFF_BM + nb * CHUNK_BYTES,
                     (const char*)g_bm + (size_t)(ch + 1) * CHUNK_BYTES, CHUNK_BYTES, mb);
        }
        mbar_wait((ch & 1) ? mb_bm1 : mb_bm0, (ch >> 1) & 1);

        const ulonglong2* bmc = (const ulonglong2*)(sm_ + OFF_BM + (ch & 1) * CHUNK_BYTES);
        // warp handles f's of its parity: 16 per chunk, 8 k's each
        #pragma unroll 4
        for (int it = 0; it < 16; it++) {
            int fc = 2 * it + sub;
            float2 ad = adjw[fc * 32 + lane];
            unsigned long long uu = pack2(ad.x, ad.x);
            unsigned long long vv = pack2(ad.y, ad.y);
            const ulonglong2* bp = bmc + fc * 20 + 4 * g;
            ulonglong2 q0 = bp[0];
            ulonglong2 q1 = bp[1];
            ulonglong2 q2 = bp[2];
            ulonglong2 q3 = bp[3];
            fma2(accA[0], uu, q0.x); fma2(accB[0], vv, q0.x);
            fma2(accA[1], uu, q0.y); fma2(accB[1], vv, q0.y);
            fma2(accA[2], uu, q1.x); fma2(accB[2], vv, q1.x);
            fma2(accA[3], uu, q1.y); fma2(accB[3], vv, q1.y);
            fma2(accA[4], uu, q2.x); fma2(accB[4], vv, q2.x);
            fma2(accA[5], uu, q2.y); fma2(accB[5], vv, q2.y);
            fma2(accA[6], uu, q3.x); fma2(accB[6], vv, q3.x);
            fma2(accA[7], uu, q3.y); fma2(accB[7], vv, q3.y);
        }
    }
    __syncthreads();

    // ---- cross-sub partial reduction (sub1 -> sub0) ----
    {
        ulonglong2* part = (ulonglong2*)(sm_);   // 5*32*8 ull2 = 20480 B (gs dead)
        if (sub == 1) {
            ulonglong2* dst = part + (g * 32 + lane) * 8;
            #pragma unroll
            for (int kk = 0; kk < 8; kk++)
                dst[kk] = make_ulonglong2(accA[kk], accB[kk]);
        }
        __syncthreads();
        if (sub == 0) {
            const ulonglong2* src = part + (g * 32 + lane) * 8;
            #pragma unroll
            for (int kk = 0; kk < 8; kk++) {
                ulonglong2 q = src[kk];
                float a0, a1, b0, b1, c0, c1, d0, d1;
                unpack2(accA[kk], a0, a1); unpack2(q.x, b0, b1);
                unpack2(accB[kk], c0, c1); unpack2(q.y, d0, d1);
                accA[kk] = pack2(a0 + b0, a1 + b1);
                accB[kk] = pack2(c0 + d0, c1 + d1);
            }
        }
        __syncthreads();   // partials consumed; region reusable as bc
    }

    // ---- epilogue: assemble band_cov, dsum, cov->pv projection ----
    float2* bc   = (float2*)(sm_);
    float*  invd = (float*)(sm_ + 20480);
    float2* ct   = (float2*)(sm_ + 20736);   // [64][65]

    if (sub == 0) {
        #pragma unroll
        for (int kk = 0; kk < 8; kk++) {
            float S1, S3, S4, S2;
            unpack2(accA[kk], S1, S3);
            unpack2(accB[kk], S4, S2);
            int k = 8 * g + kk;
            if (dg) {
                bc[k * 64 + iCh * 9] = make_float2(S1, S3);
                bc[k * 64 + jCh * 9] = make_float2(S4, S2);
            } else {
                bc[k * 64 + iCh * 8 + jCh] = make_float2(S1 - S2, S3 + S4);
                bc[k * 64 + jCh * 8 + iCh] = make_float2(S1 + S2, S3 - S4);
            }
        }
    }
    __syncthreads();

    if (tid < 40) {
        float s = 0.f;
        #pragma unroll
        for (int d = 0; d < 8; d++) s += bc[tid * 64 + d * 9].x;
        invd[tid] = 1.0f / fmaxf(s, 1e-20f);
    }
    for (int idx = tid; idx < 4096; idx += NTHR) {
        int c = idx >> 6, p = idx & 63;
        ct[c * 65 + p] = g_ct[idx];
    }
    __syncthreads();

    const unsigned long long* ctu = (const unsigned long long*)ct;
    const unsigned long long* bcu = (const unsigned long long*)bc;
    const int p  = tid & 63;
    const int kq = tid >> 6;         // 0..4, warp-uniform
    unsigned long long acc[8] = {0,0,0,0,0,0,0,0};
    #pragma unroll 4
    for (int c = 0; c < 64; c++) {
        unsigned long long m = ctu[c * 65 + p];
        #pragma unroll
        for (int r = 0; r < 8; r++)
            fma2(acc[r], m, bcu[(kq + 5 * r) * 64 + c]);
    }
    float* zt = g_z + (size_t)tile * 2560;
    #pragma unroll
    for (int r = 0; r < 8; r++) {
        int k = kq + 5 * r;
        float lo, hi; unpack2(acc[r], lo, hi);
        zt[k * 64 + p] = (lo - hi) * invd[k];   // Re(c2p·y) / dsum
    }
}

// ---- IIR pass 1: chunk finals only (16 chunks of 25 frames) ----
__global__ void __launch_bounds__(256) iir_pass1(const float* __restrict__ tau)
{
    int tid = blockIdx.x * 256 + threadIdx.x;   // 81920 = B*16*K*P
    int p = tid & 63;
    int k = (tid >> 6) % 40;
    int ch = (tid / 2560) & 15;
    int b = tid / 40960;
    float a = tau[k], om = 1.0f - a;
    size_t base = ((size_t)b * 400 + ch * 25) * 2560 + k * 64 + p;
    float y = 0.f;
    #pragma unroll 5
    for (int i = 0; i < 25; i++)
        y = a * y + om * g_z[base + (size_t)i * 2560];
    g_cf[((b * 16 + ch) * 40 + k) * 64 + p] = y;
}

// ---- IIR pass 2: inline carry combine + full scan, single out write ----
__global__ void __launch_bounds__(256) iir_pass2(const float* __restrict__ tau,
                                                 float* __restrict__ out)
{
    int tid = blockIdx.x * 256 + threadIdx.x;
    int p = tid & 63;
    int k = (tid >> 6) % 40;
    int ch = (tid / 2560) & 15;
    int b = tid / 40960;
    float a = tau[k], om = 1.0f - a;
    float a2 = a * a, a4 = a2 * a2, a8 = a4 * a4, a16 = a8 * a8;
    float a25 = a16 * a8 * a;

    float cf[16];
    #pragma unroll
    for (int j = 0; j < 15; j++)
        cf[j] = (j < ch) ? g_cf[((b * 16 + j) * 40 + k) * 64 + p] : 0.f;
    float y = 0.f;
    #pragma unroll
    for (int j = 0; j < 15; j++)
        if (j < ch) y = cf[j] + a25 * y;

    size_t base = ((size_t)b * 400 + ch * 25) * 2560 + k * 64 + p;
    #pragma unroll 5
    for (int i = 0; i < 25; i++) {
        y = a * y + om * g_z[base + (size_t)i * 2560];
        out[base + (size_t)i * 2560] = y;
    }
}

extern "C" void kernel_launch(void* const* d_in, const int* in_sizes, int n_in,
                              void* d_out, int out_size)
{
    const float* br  = (const float*)d_in[0];
    const float* bi  = (const float*)d_in[1];
    const float* bmr = (const float*)d_in[2];
    const float* bmi = (const float*)d_in[3];
    const float* pr  = (const float*)d_in[4];
    const float* pi  = (const float*)d_in[5];
    const float* tau = (const float*)d_in[6];

    cudaFuncSetAttribute(pv_main, cudaFuncAttributeMaxDynamicSharedMemorySize, SMEM_TOTAL);

    prep<<<96, 256>>>(bmr, bmi, pr, pi);
    pv_main<<<TILES, NTHR, SMEM_TOTAL>>>(br, bi);
    iir_pass1<<<320, 256>>>(tau);
    iir_pass2<<<320, 256>>>(tau, (float*)d_out);
}

// round 8
// speedup vs baseline: 1.2882x; 1.2882x over previous
#include <cuda_runtime.h>

#define TILES 800
#define NTHR  256   // 8 warps: warp w = k-quintet (k = 5w..5w+4), lane = pair

__device__ float  g_z[2 * 400 * 40 * 64];   // pre-IIR projected values (B,T,K,P)
__device__ float  g_cf[2 * 16 * 40 * 64];   // chunk-final y
// permuted bm: [chunk ch][group g][fc][5 x float2]  (chunk = 32 f, group = 5 ks)
__device__ __align__(16) float2 g_bm[512 * 40];
__device__ __align__(16) float2 g_ct[64 * 64];   // c2p transposed [c][p]

// item table: bits[0:8)=i, [8:16)=j, bit16 = diag-pseudo-pair flag
__constant__ unsigned PAIR_TBL[32] = {
  0x0100,0x0200,0x0300,0x0400,0x0500,0x0600,0x0700,
  0x0201,0x0301,0x0401,0x0501,0x0601,0x0701,
  0x0302,0x0402,0x0502,0x0602,0x0702,
  0x0403,0x0503,0x0603,0x0703,
  0x0504,0x0604,0x0704,
  0x0605,0x0705,
  0x0706,
  0x10100,0x10302,0x10504,0x10706
};

// ---- smem layout (bytes), total 69984 -> 3 CTAs/SM ----
// [0,33088)       gs float2[8][517]
//                 epilogue overlay: bc2 f2[64][44] @0 (22528) | invd @22528 | ct f2[64][65] @22720 (33280)
// [33088,49472)   adj double buffer: 2 x 8192 (32f x 32 pairs float2)
// [49472,69952)   bm double buffer:  2 x 10240 (permuted chunks)
//   prologue overlay: brs float[4096]@33088, bis float[4096]@49472
// [69952,69984)   mbarriers: mb_x, mb_bm0, mb_bm1
#define OFF_GS   0
#define OFF_ADJ  33088
#define OFF_BM   49472
#define OFF_BRS  33088
#define OFF_BIS  49472
#define OFF_MB   69952
#define SMEM_TOTAL 69984
#define CHUNKS 16          // 32 f each
#define CHUNK_BYTES 10240

#define OFF_BC   0
#define OFF_INVD 22528
#define OFF_CT   22720

__device__ __forceinline__ unsigned long long pack2(float a, float b) {
    unsigned long long r;
    asm("mov.b64 %0, {%1,%2};" : "=l"(r) : "f"(a), "f"(b));
    return r;
}
__device__ __forceinline__ void fma2(unsigned long long& acc,
                                     unsigned long long a, unsigned long long b) {
    asm("fma.rn.f32x2 %0, %1, %2, %0;" : "+l"(acc) : "l"(a), "l"(b));
}
__device__ __forceinline__ void unpack2(unsigned long long x, float& lo, float& hi) {
    asm("mov.b64 {%0,%1}, %2;" : "=f"(lo), "=f"(hi) : "l"(x));
}
__device__ __forceinline__ void mbar_init(unsigned mbar, unsigned cnt) {
    asm volatile("mbarrier.init.shared.b64 [%0], %1;" :: "r"(mbar), "r"(cnt) : "memory");
}
__device__ __forceinline__ void mbar_expect(unsigned mbar, unsigned bytes) {
    asm volatile("mbarrier.arrive.expect_tx.shared.b64 _, [%0], %1;"
                 :: "r"(mbar), "r"(bytes) : "memory");
}
__device__ __forceinline__ void bulk_g2s(unsigned dst, const void* src,
                                         unsigned bytes, unsigned mbar) {
    asm volatile("cp.async.bulk.shared::cluster.global.mbarrier::complete_tx::bytes "
                 "[%0], [%1], %2, [%3];"
                 :: "r"(dst), "l"(src), "r"(bytes), "r"(mbar) : "memory");
}
__device__ __forceinline__ void mbar_wait(unsigned mbar, unsigned parity) {
    asm volatile(
        "{\n\t.reg .pred P1;\n\t"
        "WL_%=:\n\t"
        "mbarrier.try_wait.parity.acquire.cta.shared::cta.b64 P1, [%0], %1, 0x989680;\n\t"
        "@P1 bra.uni WD_%=;\n\t"
        "bra.uni WL_%=;\n\t"
        "WD_%=:\n\t}"
        :: "r"(mbar), "r"(parity) : "memory");
}

extern __shared__ char sm_[];

// ---- prep: permuted bm + transposed c2p (runs every launch) ----
__global__ void __launch_bounds__(256) prep(
    const float* __restrict__ bmr, const float* __restrict__ bmi,
    const float* __restrict__ pr,  const float* __restrict__ pi)
{
    int t = blockIdx.x * 256 + threadIdx.x;
    if (t < 20480) {
        int f = t / 40, k = t % 40;
        int ch = f >> 5, fc = f & 31;
        int g = k / 5, kk = k % 5;
        g_bm[ch * 1280 + g * 160 + fc * 5 + kk] = make_float2(bmr[t], bmi[t]);
    } else {
        int i = t - 20480;
        if (i < 4096) {
            int p = i >> 6, c = i & 63;
            g_ct[c * 64 + p] = make_float2(pr[i], pi[i]);
        }
    }
}

__global__ void __launch_bounds__(NTHR, 3) pv_main(
    const float* __restrict__ br,  const float* __restrict__ bi)
{
    float*  brs = (float*)(sm_ + OFF_BRS);
    float*  bis = (float*)(sm_ + OFF_BIS);
    float2* gs  = (float2*)(sm_ + OFF_GS);
    const unsigned sbase = (unsigned)__cvta_generic_to_shared(sm_);
    const unsigned mb_x   = sbase + OFF_MB;
    const unsigned mb_bm0 = sbase + OFF_MB + 8;
    const unsigned mb_bm1 = sbase + OFF_MB + 16;

    const int tid  = threadIdx.x;
    const int tile = blockIdx.x;
    const int lane = tid & 31;
    const int w    = tid >> 5;   // 0..7: k-quintet (k = 5w..5w+4)

    if (tid == 0) {
        mbar_init(mb_x, 1);
        mbar_init(mb_bm0, 1);
        mbar_init(mb_bm1, 1);
        asm volatile("fence.proxy.async.shared::cta;" ::: "memory");
    }
    __syncthreads();
    if (tid == 0) {
        mbar_expect(mb_x, 32768);
        bulk_g2s(sbase + OFF_BRS, br + (size_t)tile * 4096, 16384, mb_x);
        bulk_g2s(sbase + OFF_BIS, bi + (size_t)tile * 4096, 16384, mb_x);
    }
    mbar_wait(mb_x, 0);

    // ---- step 1: per (c,f): (|x|^2, rsqrt) into gs ----
    #pragma unroll
    for (int r = 0; r < 16; r++) {
        int t = tid + r * NTHR;
        int c = t >> 9, f = t & 511;
        float re = brs[t], im = bis[t];
        float n = re * re + im * im;
        gs[c * 517 + f] = make_float2(n, rsqrtf(fmaxf(n, 1e-37f)));
    }
    __syncthreads();

    // ---- step 2: trace-normalised amplitude ----
    #pragma unroll
    for (int r = 0; r < 2; r++) {
        int f = tid + r * NTHR;
        float tr = 0.f;
        #pragma unroll
        for (int c = 0; c < 8; c++) tr += gs[c * 517 + f].x;
        float sit = rsqrtf(fmaxf(tr, 1e-20f));
        #pragma unroll
        for (int c = 0; c < 8; c++) {
            float2 v = gs[c * 517 + f];
            gs[c * 517 + f].x = v.x * v.y * sit;
        }
    }
    __syncthreads();

    // ---- step 3: g_c[f] = a_c[f] * r[fm] * r[fp] * conj(x[fm]) * x[fp] ----
    float2 gv[16];
    #pragma unroll
    for (int r = 0; r < 16; r++) {
        int t = tid + r * NTHR;
        int c = t >> 9, f = t & 511;
        int fm = min(max(f - 1, 0), 509), fp = fm + 2;
        float a  = gs[c * 517 + f].x;
        float rm = gs[c * 517 + fm].y, rp = gs[c * 517 + fp].y;
        float xmr = brs[c * 512 + fm], xmi = bis[c * 512 + fm];
        float xpr = brs[c * 512 + fp], xpi = bis[c * 512 + fp];
        float tre = xmr * xpr + xmi * xpi;
        float tim = xmr * xpi - xmi * xpr;
        float s = a * rm * rp;
        gv[r] = make_float2(s * tre, s * tim);
    }
    __syncthreads();
    #pragma unroll
    for (int r = 0; r < 16; r++) {
        int t = tid + r * NTHR;
        int c = t >> 9, f = t & 511;
        gs[c * 517 + f] = gv[r];
    }
    __syncthreads();   // brs/bis dead -> bm region free
    if (tid == 0) {
        mbar_expect(mb_bm0, CHUNK_BYTES);
        bulk_g2s(sbase + OFF_BM, (const char*)g_bm, CHUNK_BYTES, mb_bm0);
    }

    // ---- main loop: adj (32-f, double-buffered) + TMA bm ring + packed GEMM ----
    const unsigned e = PAIR_TBL[lane];
    const int iCh = e & 255, jCh = (e >> 8) & 255;
    const bool dg = (e & 0x10000u) != 0;

    unsigned long long accA[5] = {0,0,0,0,0};
    unsigned long long accB[5] = {0,0,0,0,0};

    #pragma unroll 1
    for (int ch = 0; ch < CHUNKS; ch++) {
        float2* adjw = (float2*)(sm_ + OFF_ADJ + (ch & 1) * 8192);
        #pragma unroll
        for (int r = 0; r < 4; r++) {
            int fc = w + r * 8;
            int f = ch * 32 + fc;
            float2 gi = gs[iCh * 517 + f], gj = gs[jCh * 517 + f];
            float u, v;
            if (dg) { u = gi.x*gi.x + gi.y*gi.y;  v = gj.x*gj.x + gj.y*gj.y; }
            else    { u = gi.x*gj.x + gi.y*gj.y;  v = gi.y*gj.x - gi.x*gj.y; }
            adjw[fc * 32 + lane] = make_float2(u, v);
        }
        __syncthreads();   // adj(ch) visible; gemm(ch-1) done -> bm slot (ch+1)&1 free
        if (ch + 1 < CHUNKS && tid == 0) {
            int nb = (ch + 1) & 1;
            unsigned mb = nb ? mb_bm1 : mb_bm0;
            mbar_expect(mb, CHUNK_BYTES);
            bulk_g2s(sbase + OFF_BM + nb * CHUNK_BYTES,
                     (const char*)g_bm + (size_t)(ch + 1) * CHUNK_BYTES, CHUNK_BYTES, mb);
        }
        mbar_wait((ch & 1) ? mb_bm1 : mb_bm0, (ch >> 1) & 1);

        // warp's contiguous 1280B slice: [32 fc][5 float2]
        const ulonglong2* slice =
            (const ulonglong2*)(sm_ + OFF_BM + (ch & 1) * CHUNK_BYTES + w * 1280);
        #pragma unroll 4
        for (int it = 0; it < 16; it++) {
            int f0 = 2 * it, f1 = 2 * it + 1;
            float2 a0 = adjw[f0 * 32 + lane];
            float2 a1 = adjw[f1 * 32 + lane];
            unsigned long long uu0 = pack2(a0.x, a0.x), vv0 = pack2(a0.y, a0.y);
            unsigned long long uu1 = pack2(a1.x, a1.x), vv1 = pack2(a1.y, a1.y);
            ulonglong2 q0 = slice[it * 5 + 0];   // f0: kk0,kk1
            ulonglong2 q1 = slice[it * 5 + 1];   // f0: kk2,kk3
            ulonglong2 q2 = slice[it * 5 + 2];   // f0: kk4 | f1: kk0
            ulonglong2 q3 = slice[it * 5 + 3];   // f1: kk1,kk2
            ulonglong2 q4 = slice[it * 5 + 4];   // f1: kk3,kk4
            fma2(accA[0], uu0, q0.x); fma2(accB[0], vv0, q0.x);
            fma2(accA[1], uu0, q0.y); fma2(accB[1], vv0, q0.y);
            fma2(accA[2], uu0, q1.x); fma2(accB[2], vv0, q1.x);
            fma2(accA[3], uu0, q1.y); fma2(accB[3], vv0, q1.y);
            fma2(accA[4], uu0, q2.x); fma2(accB[4], vv0, q2.x);
            fma2(accA[0], uu1, q2.y); fma2(accB[0], vv1, q2.y);
            fma2(accA[1], uu1, q3.x); fma2(accB[1], vv1, q3.x);
            fma2(accA[2], uu1, q3.y); fma2(accB[2], vv1, q3.y);
            fma2(accA[3], uu1, q4.x); fma2(accB[3], vv1, q4.x);
            fma2(accA[4], uu1, q4.y); fma2(accB[4], vv1, q4.y);
        }
    }
    __syncthreads();

    // ---- epilogue: assemble band_cov (bc2[c2][44 k]), dsum, projection ----
    float2* bc   = (float2*)(sm_ + OFF_BC);
    float*  invd = (float*)(sm_ + OFF_INVD);
    float2* ct   = (float2*)(sm_ + OFF_CT);   // [64][65]

    #pragma unroll
    for (int kk = 0; kk < 5; kk++) {
        float S1, S3, S4, S2;
        unpack2(accA[kk], S1, S3);
        unpack2(accB[kk], S4, S2);
        int k = 5 * w + kk;
        if (dg) {
            bc[(iCh * 9) * 44 + k] = make_float2(S1, S3);
            bc[(jCh * 9) * 44 + k] = make_float2(S4, S2);
        } else {
            bc[(iCh * 8 + jCh) * 44 + k] = make_float2(S1 - S2, S3 + S4);
            bc[(jCh * 8 + iCh) * 44 + k] = make_float2(S1 + S2, S3 - S4);
        }
    }
    __syncthreads();

    if (tid < 40) {
        float s = 0.f;
        #pragma unroll
        for (int d = 0; d < 8; d++) s += bc[(d * 9) * 44 + tid].x;
        invd[tid] = 1.0f / fmaxf(s, 1e-20f);
    }
    #pragma unroll
    for (int r = 0; r < 16; r++) {
        int idx = tid + r * NTHR;
        int c = idx >> 6, p = idx & 63;
        ct[c * 65 + p] = g_ct[idx];
    }
    __syncthreads();

    // thread -> p = tid&63, k = 10*kq + r (contiguous -> uniform LDS.128 on bc)
    const unsigned long long* ctu = (const unsigned long long*)ct;
    const unsigned long long* bcu = (const unsigned long long*)bc;
    const int p  = tid & 63;
    const int kq = tid >> 6;         // 0..3, warp-uniform
    unsigned long long acc[10] = {0,0,0,0,0,0,0,0,0,0};
    #pragma unroll 4
    for (int c = 0; c < 64; c++) {
        unsigned long long m = ctu[c * 65 + p];
        const unsigned long long* bp = bcu + c * 44 + 10 * kq;
        #pragma unroll
        for (int r = 0; r < 10; r++)
            fma2(acc[r], m, bp[r]);
    }
    float* zt = g_z + (size_t)tile * 2560;
    #pragma unroll
    for (int r = 0; r < 10; r++) {
        int k = 10 * kq + r;
        float lo, hi; unpack2(acc[r], lo, hi);
        zt[k * 64 + p] = (lo - hi) * invd[k];   // Re(c2p·y) / dsum
    }
}

// ---- IIR pass 1: chunk finals only (16 chunks of 25 frames) ----
__global__ void __launch_bounds__(256) iir_pass1(const float* __restrict__ tau)
{
    int tid = blockIdx.x * 256 + threadIdx.x;   // 81920 = B*16*K*P
    int p = tid & 63;
    int k = (tid >> 6) % 40;
    int ch = (tid / 2560) & 15;
    int b = tid / 40960;
    float a = tau[k], om = 1.0f - a;
    size_t base = ((size_t)b * 400 + ch * 25) * 2560 + k * 64 + p;
    float y = 0.f;
    #pragma unroll 5
    for (int i = 0; i < 25; i++)
        y = a * y + om * g_z[base + (size_t)i * 2560];
    g_cf[((b * 16 + ch) * 40 + k) * 64 + p] = y;
}

// ---- IIR pass 2: inline carry combine + full scan, single out write ----
__global__ void __launch_bounds__(256) iir_pass2(const float* __restrict__ tau,
                                                 float* __restrict__ out)
{
    int tid = blockIdx.x * 256 + threadIdx.x;
    int p = tid & 63;
    int k = (tid >> 6) % 40;
    int ch = (tid / 2560) & 15;
    int b = tid / 40960;
    float a = tau[k], om = 1.0f - a;
    float a2 = a * a, a4 = a2 * a2, a8 = a4 * a4, a16 = a8 * a8;
    float a25 = a16 * a8 * a;

    float cf[16];
    #pragma unroll
    for (int j = 0; j < 15; j++)
        cf[j] = (j < ch) ? g_cf[((b * 16 + j) * 40 + k) * 64 + p] : 0.f;
    float y = 0.f;
    #pragma unroll
    for (int j = 0; j < 15; j++)
        if (j < ch) y = cf[j] + a25 * y;

    size_t base = ((size_t)b * 400 + ch * 25) * 2560 + k * 64 + p;
    #pragma unroll 5
    for (int i = 0; i < 25; i++) {
        y = a * y + om * g_z[base + (size_t)i * 2560];
        out[base + (size_t)i * 2560] = y;
    }
}

extern "C" void kernel_launch(void* const* d_in, const int* in_sizes, int n_in,
                              void* d_out, int out_size)
{
    const float* br  = (const float*)d_in[0];
    const float* bi  = (const float*)d_in[1];
    const float* bmr = (const float*)d_in[2];
    const float* bmi = (const float*)d_in[3];
    const float* pr  = (const float*)d_in[4];
    const float* pi  = (const float*)d_in[5];
    const float* tau = (const float*)d_in[6];

    cudaFuncSetAttribute(pv_main, cudaFuncAttributeMaxDynamicSharedMemorySize, SMEM_TOTAL);

    prep<<<96, 256>>>(bmr, bmi, pr, pi);
    pv_main<<<TILES, NTHR, SMEM_TOTAL>>>(br, bi);
    iir_pass1<<<320, 256>>>(tau);
    iir_pass2<<<320, 256>>>(tau, (float*)d_out);
}

// round 9
// speedup vs baseline: 1.2887x; 1.0004x over previous
#include <cuda_runtime.h>

#define TILES 800
#define NTHR  256   // 8 warps: warp w = k-quintet (k = 5w..5w+4), lane = pair

__device__ float  g_z[2 * 400 * 40 * 64];   // pre-IIR projected values (B,T,K,P)
__device__ float  g_cf[2 * 16 * 40 * 64];   // chunk-final y
// permuted bm: [chunk ch][group g][fc][5 x float2]  (chunk = 32 f, group = 5 ks)
__device__ __align__(16) float2 g_bm[512 * 40];
__device__ __align__(16) float2 g_ct[64 * 64];   // c2p transposed [c][p]

// item table: bits[0:8)=i, [8:16)=j, bit16 = diag-pseudo-pair flag
__constant__ unsigned PAIR_TBL[32] = {
  0x0100,0x0200,0x0300,0x0400,0x0500,0x0600,0x0700,
  0x0201,0x0301,0x0401,0x0501,0x0601,0x0701,
  0x0302,0x0402,0x0502,0x0602,0x0702,
  0x0403,0x0503,0x0603,0x0703,
  0x0504,0x0604,0x0704,
  0x0605,0x0705,
  0x0706,
  0x10100,0x10302,0x10504,0x10706
};

// ---- smem layout (bytes), total 69984 -> 3 CTAs/SM ----
// [0,33088)       gs float2[8][517]
//                 epilogue overlay: bc2 f2[64][44] @0 (22528) | invd @22528 | ct f2[64][65] @22720 (33280)
// [33088,49472)   adj double buffer: 2 x 8192 (32f x 32 pairs float2)
// [49472,69952)   bm double buffer:  2 x 10240 (permuted chunks)
//   prologue overlay: brs float[4096]@33088, bis float[4096]@49472
// [69952,69984)   mbarriers: mb_x, mb_bm0, mb_bm1
#define OFF_GS   0
#define OFF_ADJ  33088
#define OFF_BM   49472
#define OFF_BRS  33088
#define OFF_BIS  49472
#define OFF_MB   69952
#define SMEM_TOTAL 69984
#define CHUNKS 16          // 32 f each
#define CHUNK_BYTES 10240

#define OFF_BC   0
#define OFF_INVD 22528
#define OFF_CT   22720

__device__ __forceinline__ unsigned long long pack2(float a, float b) {
    unsigned long long r;
    asm("mov.b64 %0, {%1,%2};" : "=l"(r) : "f"(a), "f"(b));
    return r;
}
__device__ __forceinline__ void fma2(unsigned long long& acc,
                                     unsigned long long a, unsigned long long b) {
    asm("fma.rn.f32x2 %0, %1, %2, %0;" : "+l"(acc) : "l"(a), "l"(b));
}
__device__ __forceinline__ void unpack2(unsigned long long x, float& lo, float& hi) {
    asm("mov.b64 {%0,%1}, %2;" : "=f"(lo), "=f"(hi) : "l"(x));
}
__device__ __forceinline__ void mbar_init(unsigned mbar, unsigned cnt) {
    asm volatile("mbarrier.init.shared.b64 [%0], %1;" :: "r"(mbar), "r"(cnt) : "memory");
}
__device__ __forceinline__ void mbar_expect(unsigned mbar, unsigned bytes) {
    asm volatile("mbarrier.arrive.expect_tx.shared.b64 _, [%0], %1;"
                 :: "r"(mbar), "r"(bytes) : "memory");
}
__device__ __forceinline__ void bulk_g2s(unsigned dst, const void* src,
                                         unsigned bytes, unsigned mbar) {
    asm volatile("cp.async.bulk.shared::cluster.global.mbarrier::complete_tx::bytes "
                 "[%0], [%1], %2, [%3];"
                 :: "r"(dst), "l"(src), "r"(bytes), "r"(mbar) : "memory");
}
__device__ __forceinline__ void mbar_wait(unsigned mbar, unsigned parity) {
    asm volatile(
        "{\n\t.reg .pred P1;\n\t"
        "WL_%=:\n\t"
        "mbarrier.try_wait.parity.acquire.cta.shared::cta.b64 P1, [%0], %1, 0x989680;\n\t"
        "@P1 bra.uni WD_%=;\n\t"
        "bra.uni WL_%=;\n\t"
        "WD_%=:\n\t}"
        :: "r"(mbar), "r"(parity) : "memory");
}

extern __shared__ char sm_[];

// ---- prep: permuted bm + transposed c2p (runs every launch) ----
__global__ void __launch_bounds__(256) prep(
    const float* __restrict__ bmr, const float* __restrict__ bmi,
    const float* __restrict__ pr,  const float* __restrict__ pi)
{
    int t = blockIdx.x * 256 + threadIdx.x;
    if (t < 20480) {
        int f = t / 40, k = t % 40;
        int ch = f >> 5, fc = f & 31;
        int g = k / 5, kk = k % 5;
        g_bm[ch * 1280 + g * 160 + fc * 5 + kk] = make_float2(bmr[t], bmi[t]);
    } else {
        int i = t - 20480;
        if (i < 4096) {
            int p = i >> 6, c = i & 63;
            g_ct[c * 64 + p] = make_float2(pr[i], pi[i]);
        }
    }
}

__global__ void __launch_bounds__(NTHR, 3) pv_main(
    const float* __restrict__ br,  const float* __restrict__ bi)
{
    float*  brs = (float*)(sm_ + OFF_BRS);
    float*  bis = (float*)(sm_ + OFF_BIS);
    float2* gs  = (float2*)(sm_ + OFF_GS);
    const unsigned sbase = (unsigned)__cvta_generic_to_shared(sm_);
    const unsigned mb_x   = sbase + OFF_MB;
    const unsigned mb_bm0 = sbase + OFF_MB + 8;
    const unsigned mb_bm1 = sbase + OFF_MB + 16;

    const int tid  = threadIdx.x;
    const int tile = blockIdx.x;
    const int lane = tid & 31;
    const int w    = tid >> 5;   // 0..7: k-quintet (k = 5w..5w+4)

    if (tid == 0) {
        mbar_init(mb_x, 1);
        mbar_init(mb_bm0, 1);
        mbar_init(mb_bm1, 1);
        asm volatile("fence.proxy.async.shared::cta;" ::: "memory");
    }
    __syncthreads();
    if (tid == 0) {
        mbar_expect(mb_x, 32768);
        bulk_g2s(sbase + OFF_BRS, br + (size_t)tile * 4096, 16384, mb_x);
        bulk_g2s(sbase + OFF_BIS, bi + (size_t)tile * 4096, 16384, mb_x);
    }
    mbar_wait(mb_x, 0);

    // ---- step 1: per (c,f): (|x|^2, rsqrt) into gs ----
    #pragma unroll
    for (int r = 0; r < 16; r++) {
        int t = tid + r * NTHR;
        int c = t >> 9, f = t & 511;
        float re = brs[t], im = bis[t];
        float n = re * re + im * im;
        gs[c * 517 + f] = make_float2(n, rsqrtf(fmaxf(n, 1e-37f)));
    }
    __syncthreads();

    // ---- step 2: trace-normalised amplitude ----
    #pragma unroll
    for (int r = 0; r < 2; r++) {
        int f = tid + r * NTHR;
        float tr = 0.f;
        #pragma unroll
        for (int c = 0; c < 8; c++) tr += gs[c * 517 + f].x;
        float sit = rsqrtf(fmaxf(tr, 1e-20f));
        #pragma unroll
        for (int c = 0; c < 8; c++) {
            float2 v = gs[c * 517 + f];
            gs[c * 517 + f].x = v.x * v.y * sit;
        }
    }
    __syncthreads();

    // ---- step 3: g_c[f] = a_c[f] * r[fm] * r[fp] * conj(x[fm]) * x[fp] ----
    float2 gv[16];
    #pragma unroll
    for (int r = 0; r < 16; r++) {
        int t = tid + r * NTHR;
        int c = t >> 9, f = t & 511;
        int fm = min(max(f - 1, 0), 509), fp = fm + 2;
        float a  = gs[c * 517 + f].x;
        float rm = gs[c * 517 + fm].y, rp = gs[c * 517 + fp].y;
        float xmr = brs[c * 512 + fm], xmi = bis[c * 512 + fm];
        float xpr = brs[c * 512 + fp], xpi = bis[c * 512 + fp];
        float tre = xmr * xpr + xmi * xpi;
        float tim = xmr * xpi - xmi * xpr;
        float s = a * rm * rp;
        gv[r] = make_float2(s * tre, s * tim);
    }
    __syncthreads();
    #pragma unroll
    for (int r = 0; r < 16; r++) {
        int t = tid + r * NTHR;
        int c = t >> 9, f = t & 511;
        gs[c * 517 + f] = gv[r];
    }
    __syncthreads();   // brs/bis dead -> bm region free
    if (tid == 0) {
        mbar_expect(mb_bm0, CHUNK_BYTES);
        bulk_g2s(sbase + OFF_BM, (const char*)g_bm, CHUNK_BYTES, mb_bm0);
    }

    // ---- main loop: adj (32-f, double-buffered) + TMA bm ring + packed GEMM ----
    const unsigned e = PAIR_TBL[lane];
    const int iCh = e & 255, jCh = (e >> 8) & 255;
    const bool dg = (e & 0x10000u) != 0;

    unsigned long long accA[5] = {0,0,0,0,0};
    unsigned long long accB[5] = {0,0,0,0,0};

    #pragma unroll 1
    for (int ch = 0; ch < CHUNKS; ch++) {
        float2* adjw = (float2*)(sm_ + OFF_ADJ + (ch & 1) * 8192);
        #pragma unroll
        for (int r = 0; r < 4; r++) {
            int fc = w + r * 8;
            int f = ch * 32 + fc;
            float2 gi = gs[iCh * 517 + f], gj = gs[jCh * 517 + f];
            float u, v;
            if (dg) { u = gi.x*gi.x + gi.y*gi.y;  v = gj.x*gj.x + gj.y*gj.y; }
            else    { u = gi.x*gj.x + gi.y*gj.y;  v = gi.y*gj.x - gi.x*gj.y; }
            adjw[fc * 32 + lane] = make_float2(u, v);
        }
        __syncthreads();   // adj(ch) visible; gemm(ch-1) done -> bm slot (ch+1)&1 free
        if (ch + 1 < CHUNKS && tid == 0) {
            int nb = (ch + 1) & 1;
            unsigned mb = nb ? mb_bm1 : mb_bm0;
            mbar_expect(mb, CHUNK_BYTES);
            bulk_g2s(sbase + OFF_BM + nb * CHUNK_BYTES,
                     (const char*)g_bm + (size_t)(ch + 1) * CHUNK_BYTES, CHUNK_BYTES, mb);
        }
        mbar_wait((ch & 1) ? mb_bm1 : mb_bm0, (ch >> 1) & 1);

        // warp's contiguous 1280B slice: [32 fc][5 float2]
        const ulonglong2* slice =
            (const ulonglong2*)(sm_ + OFF_BM + (ch & 1) * CHUNK_BYTES + w * 1280);
        #pragma unroll 4
        for (int it = 0; it < 16; it++) {
            int f0 = 2 * it, f1 = 2 * it + 1;
            float2 a0 = adjw[f0 * 32 + lane];
            float2 a1 = adjw[f1 * 32 + lane];
            unsigned long long uu0 = pack2(a0.x, a0.x), vv0 = pack2(a0.y, a0.y);
            unsigned long long uu1 = pack2(a1.x, a1.x), vv1 = pack2(a1.y, a1.y);
            ulonglong2 q0 = slice[it * 5 + 0];   // f0: kk0,kk1
            ulonglong2 q1 = slice[it * 5 + 1];   // f0: kk2,kk3
            ulonglong2 q2 = slice[it * 5 + 2];   // f0: kk4 | f1: kk0
            ulonglong2 q3 = slice[it * 5 + 3];   // f1: kk1,kk2
            ulonglong2 q4 = slice[it * 5 + 4];   // f1: kk3,kk4
            fma2(accA[0], uu0, q0.x); fma2(accB[0], vv0, q0.x);
            fma2(accA[1], uu0, q0.y); fma2(accB[1], vv0, q0.y);
            fma2(accA[2], uu0, q1.x); fma2(accB[2], vv0, q1.x);
            fma2(accA[3], uu0, q1.y); fma2(accB[3], vv0, q1.y);
            fma2(accA[4], uu0, q2.x); fma2(accB[4], vv0, q2.x);
            fma2(accA[0], uu1, q2.y); fma2(accB[0], vv1, q2.y);
            fma2(accA[1], uu1, q3.x); fma2(accB[1], vv1, q3.x);
            fma2(accA[2], uu1, q3.y); fma2(accB[2], vv1, q3.y);
            fma2(accA[3], uu1, q4.x); fma2(accB[3], vv1, q4.x);
            fma2(accA[4], uu1, q4.y); fma2(accB[4], vv1, q4.y);
        }
    }
    __syncthreads();

    // ---- epilogue: assemble band_cov (bc2[c2][44 k]), dsum, projection ----
    float2* bc   = (float2*)(sm_ + OFF_BC);
    float*  invd = (float*)(sm_ + OFF_INVD);
    float2* ct   = (float2*)(sm_ + OFF_CT);   // [64][65]

    #pragma unroll
    for (int kk = 0; kk < 5; kk++) {
        float S1, S3, S4, S2;
        unpack2(accA[kk], S1, S3);
        unpack2(accB[kk], S4, S2);
        int k = 5 * w + kk;
        if (dg) {
            bc[(iCh * 9) * 44 + k] = make_float2(S1, S3);
            bc[(jCh * 9) * 44 + k] = make_float2(S4, S2);
        } else {
            bc[(iCh * 8 + jCh) * 44 + k] = make_float2(S1 - S2, S3 + S4);
            bc[(jCh * 8 + iCh) * 44 + k] = make_float2(S1 + S2, S3 - S4);
        }
    }
    __syncthreads();

    if (tid < 40) {
        float s = 0.f;
        #pragma unroll
        for (int d = 0; d < 8; d++) s += bc[(d * 9) * 44 + tid].x;
        invd[tid] = 1.0f / fmaxf(s, 1e-20f);
    }
    #pragma unroll
    for (int r = 0; r < 16; r++) {
        int idx = tid + r * NTHR;
        int c = idx >> 6, p = idx & 63;
        ct[c * 65 + p] = g_ct[idx];
    }
    __syncthreads();

    // thread -> p = tid&63, k = 10*kq + r (contiguous -> uniform LDS.128 on bc)
    const unsigned long long* ctu = (const unsigned long long*)ct;
    const unsigned long long* bcu = (const unsigned long long*)bc;
    const int p  = tid & 63;
    const int kq = tid >> 6;         // 0..3, warp-uniform
    unsigned long long acc[10] = {0,0,0,0,0,0,0,0,0,0};
    #pragma unroll 4
    for (int c = 0; c < 64; c++) {
        unsigned long long m = ctu[c * 65 + p];
        const unsigned long long* bp = bcu + c * 44 + 10 * kq;
        #pragma unroll
        for (int r = 0; r < 10; r++)
            fma2(acc[r], m, bp[r]);
    }
    float* zt = g_z + (size_t)tile * 2560;
    #pragma unroll
    for (int r = 0; r < 10; r++) {
        int k = 10 * kq + r;
        float lo, hi; unpack2(acc[r], lo, hi);
        zt[k * 64 + p] = (lo - hi) * invd[k];   // Re(c2p·y) / dsum
    }
}

// ---- IIR pass 1: chunk finals only (16 chunks of 25 frames) ----
__global__ void __launch_bounds__(256) iir_pass1(const float* __restrict__ tau)
{
    int tid = blockIdx.x * 256 + threadIdx.x;   // 81920 = B*16*K*P
    int p = tid & 63;
    int k = (tid >> 6) % 40;
    int ch = (tid / 2560) & 15;
    int b = tid / 40960;
    float a = tau[k], om = 1.0f - a;
    size_t base = ((size_t)b * 400 + ch * 25) * 2560 + k * 64 + p;
    float y = 0.f;
    #pragma unroll 5
    for (int i = 0; i < 25; i++)
        y = a * y + om * g_z[base + (size_t)i * 2560];
    g_cf[((b * 16 + ch) * 40 + k) * 64 + p] = y;
}

// ---- IIR pass 2: inline carry combine + full scan, single out write ----
__global__ void __launch_bounds__(256) iir_pass2(const float* __restrict__ tau,
                                                 float* __restrict__ out)
{
    int tid = blockIdx.x * 256 + threadIdx.x;
    int p = tid & 63;
    int k = (tid >> 6) % 40;
    int ch = (tid / 2560) & 15;
    int b = tid / 40960;
    float a = tau[k], om = 1.0f - a;
    float a2 = a * a, a4 = a2 * a2, a8 = a4 * a4, a16 = a8 * a8;
    float a25 = a16 * a8 * a;

    float cf[16];
    #pragma unroll
    for (int j = 0; j < 15; j++)
        cf[j] = (j < ch) ? g_cf[((b * 16 + j) * 40 + k) * 64 + p] : 0.f;
    float y = 0.f;
    #pragma unroll
    for (int j = 0; j < 15; j++)
        if (j < ch) y = cf[j] + a25 * y;

    size_t base = ((size_t)b * 400 + ch * 25) * 2560 + k * 64 + p;
    #pragma unroll 5
    for (int i = 0; i < 25; i++) {
        y = a * y + om * g_z[base + (size_t)i * 2560];
        out[base + (size_t)i * 2560] = y;
    }
}

extern "C" void kernel_launch(void* const* d_in, const int* in_sizes, int n_in,
                              void* d_out, int out_size)
{
    const float* br  = (const float*)d_in[0];
    const float* bi  = (const float*)d_in[1];
    const float* bmr = (const float*)d_in[2];
    const float* bmi = (const float*)d_in[3];
    const float* pr  = (const float*)d_in[4];
    const float* pi  = (const float*)d_in[5];
    const float* tau = (const float*)d_in[6];

    cudaFuncSetAttribute(pv_main, cudaFuncAttributeMaxDynamicSharedMemorySize, SMEM_TOTAL);

    prep<<<96, 256>>>(bmr, bmi, pr, pi);
    pv_main<<<TILES, NTHR, SMEM_TOTAL>>>(br, bi);
    iir_pass1<<<320, 256>>>(tau);
    iir_pass2<<<320, 256>>>(tau, (float*)d_out);
}

// round 11
// speedup vs baseline: 1.9184x; 1.4885x over previous
#include <cuda_runtime.h>

#define TILES 800
#define NTHR  256
#define CHUNKS 16

__device__ float g_z[2 * 400 * 40 * 64];
__device__ float g_cf[2 * 16 * 40 * 64];
// bf16-split B staging: [16 ch][2 split][80 n][40 (32 k + 8 pad)] bf16 = 12800 B/chunk
__device__ __align__(16) unsigned short g_bmb[16 * 6400];
__device__ __align__(16) float2 g_ct[64 * 64];

__constant__ unsigned PAIR_TBL[32] = {
  0x0100,0x0200,0x0300,0x0400,0x0500,0x0600,0x0700,
  0x0201,0x0301,0x0401,0x0501,0x0601,0x0701,
  0x0302,0x0402,0x0502,0x0602,0x0702,
  0x0403,0x0503,0x0603,0x0703,
  0x0504,0x0604,0x0704,
  0x0605,0x0705,
  0x0706,
  0x10100,0x10302,0x10504,0x10706
};

// smem: gs 33088 @0 (epi: stg f32[64][82]=20992 @0, then ct f2[64][64]=32768 @0)
// A dbuf 2x10240 @33088 (per buf: hi[64][40]bf16 5120 + lo 5120; row stride 80B)
//   (prologue brs f32[4096] @33088)
// B dbuf 2x12800 @53568 (per buf: hi[80][40]bf16 6400 + lo 6400)
//   (prologue bis f32[4096] @53568; epilogue bc f2[64][44]=22528 @53568)
// mbars @79168: mb_x, mbB0, mbB1    invd overlays A region @33088
#define OFF_GS 0
#define OFF_A  33088
#define OFF_B  53568
#define OFF_MB 79168
#define SMEM_TOTAL 79216

__device__ __forceinline__ unsigned long long pack2(float a, float b) {
    unsigned long long r; asm("mov.b64 %0, {%1,%2};" : "=l"(r) : "f"(a), "f"(b)); return r;
}
__device__ __forceinline__ void fma2(unsigned long long& acc, unsigned long long a, unsigned long long b) {
    asm("fma.rn.f32x2 %0, %1, %2, %0;" : "+l"(acc) : "l"(a), "l"(b));
}
__device__ __forceinline__ void unpack2(unsigned long long x, float& lo, float& hi) {
    asm("mov.b64 {%0,%1}, %2;" : "=f"(lo), "=f"(hi) : "l"(x));
}
__device__ __forceinline__ unsigned f2bf(float x) {
    unsigned u = __float_as_uint(x);
    return (u + 0x7FFFu + ((u >> 16) & 1u)) >> 16;
}
__device__ __forceinline__ float bf2f(unsigned h) { return __uint_as_float(h << 16); }
__device__ __forceinline__ void mbar_init(unsigned m, unsigned c) {
    asm volatile("mbarrier.init.shared.b64 [%0], %1;" :: "r"(m), "r"(c) : "memory");
}
__device__ __forceinline__ void mbar_expect(unsigned m, unsigned b) {
    asm volatile("mbarrier.arrive.expect_tx.shared.b64 _, [%0], %1;" :: "r"(m), "r"(b) : "memory");
}
__device__ __forceinline__ void bulk_g2s(unsigned d, const void* s, unsigned b, unsigned m) {
    asm volatile("cp.async.bulk.shared::cluster.global.mbarrier::complete_tx::bytes [%0], [%1], %2, [%3];"
                 :: "r"(d), "l"(s), "r"(b), "r"(m) : "memory");
}
__device__ __forceinline__ void mbar_wait(unsigned m, unsigned p) {
    asm volatile(
        "{\n\t.reg .pred P1;\n\tWL_%=:\n\t"
        "mbarrier.try_wait.parity.acquire.cta.shared::cta.b64 P1, [%0], %1, 0x989680;\n\t"
        "@P1 bra.uni WD_%=;\n\tbra.uni WL_%=;\n\tWD_%=:\n\t}"
        :: "r"(m), "r"(p) : "memory");
}
__device__ __forceinline__ void ldsm4(unsigned* r, unsigned addr) {
    asm volatile("ldmatrix.sync.aligned.m8n8.x4.shared.b16 {%0,%1,%2,%3}, [%4];"
                 : "=r"(r[0]), "=r"(r[1]), "=r"(r[2]), "=r"(r[3]) : "r"(addr));
}
__device__ __forceinline__ void mma16816(float* d, const unsigned* a, unsigned b0, unsigned b1) {
    asm volatile("mma.sync.aligned.m16n8k16.row.col.f32.bf16.bf16.f32 "
                 "{%0,%1,%2,%3}, {%4,%5,%6,%7}, {%8,%9}, {%0,%1,%2,%3};"
                 : "+f"(d[0]), "+f"(d[1]), "+f"(d[2]), "+f"(d[3])
                 : "r"(a[0]), "r"(a[1]), "r"(a[2]), "r"(a[3]), "r"(b0), "r"(b1));
}

extern __shared__ char sm_[];

// ---- prep: bf16-split B staging + transposed c2p ----
__global__ void __launch_bounds__(256) prep(
    const float* __restrict__ bmr, const float* __restrict__ bmi,
    const float* __restrict__ pr,  const float* __restrict__ pi)
{
    int t = blockIdx.x * 256 + threadIdx.x;
    if (t < 20480) {
        int f = t / 40, k = t % 40;
        int ch = f >> 5, fc = f & 31;
        float vals[2] = {bmr[t], bmi[t]};
        #pragma unroll
        for (int e2 = 0; e2 < 2; e2++) {
            int n = 2 * k + e2;
            unsigned h = f2bf(vals[e2]);
            unsigned l = f2bf(vals[e2] - bf2f(h));
            g_bmb[ch * 6400 + n * 40 + fc] = (unsigned short)h;          // hi split
            g_bmb[ch * 6400 + 3200 + n * 40 + fc] = (unsigned short)l;   // lo split
        }
    } else {
        int i = t - 20480;
        if (i < 4096) {
            int p = i >> 6, c = i & 63;
            g_ct[c * 64 + p] = make_float2(pr[i], pi[i]);
        }
    }
}

__global__ void __launch_bounds__(NTHR, 2) pv_main(
    const float* __restrict__ br, const float* __restrict__ bi)
{
    float*  brs = (float*)(sm_ + OFF_A);
    float*  bis = (float*)(sm_ + OFF_B);
    float2* gs  = (float2*)(sm_ + OFF_GS);
    unsigned sbase;
    asm("{ .reg .u64 t; cvta.to.shared.u64 t, %1; cvt.u32.u64 %0, t; }" : "=r"(sbase) : "l"(sm_));
    const unsigned mb_x = sbase + OFF_MB, mbB0 = sbase + OFF_MB + 8, mbB1 = sbase + OFF_MB + 16;

    const int tid  = threadIdx.x;
    const int tile = blockIdx.x;
    const int lane = tid & 31;
    const int w    = tid >> 5;

    if (tid == 0) {
        mbar_init(mb_x, 1); mbar_init(mbB0, 1); mbar_init(mbB1, 1);
        asm volatile("fence.proxy.async.shared::cta;" ::: "memory");
    }
    __syncthreads();
    if (tid == 0) {
        mbar_expect(mb_x, 32768);
        bulk_g2s(sbase + OFF_A, br + (size_t)tile * 4096, 16384, mb_x);
        bulk_g2s(sbase + OFF_B, bi + (size_t)tile * 4096, 16384, mb_x);
    }
    mbar_wait(mb_x, 0);

    // step 1: (|x|^2, rsqrt)
    #pragma unroll
    for (int r = 0; r < 16; r++) {
        int t = tid + r * NTHR;
        int c = t >> 9, f = t & 511;
        float re = brs[t], im = bis[t];
        float n = re * re + im * im;
        gs[c * 517 + f] = make_float2(n, rsqrtf(fmaxf(n, 1e-37f)));
    }
    __syncthreads();
    // step 2: trace-normalised amplitude
    #pragma unroll
    for (int r = 0; r < 2; r++) {
        int f = tid + r * NTHR;
        float tr = 0.f;
        #pragma unroll
        for (int c = 0; c < 8; c++) tr += gs[c * 517 + f].x;
        float sit = rsqrtf(fmaxf(tr, 1e-20f));
        #pragma unroll
        for (int c = 0; c < 8; c++) {
            float2 v = gs[c * 517 + f];
            gs[c * 517 + f].x = v.x * v.y * sit;
        }
    }
    __syncthreads();
    // step 3: g vectors
    float2 gv[16];
    #pragma unroll
    for (int r = 0; r < 16; r++) {
        int t = tid + r * NTHR;
        int c = t >> 9, f = t & 511;
        int fm = min(max(f - 1, 0), 509), fp = fm + 2;
        float a  = gs[c * 517 + f].x;
        float rm = gs[c * 517 + fm].y, rp = gs[c * 517 + fp].y;
        float xmr = brs[c * 512 + fm], xmi = bis[c * 512 + fm];
        float xpr = brs[c * 512 + fp], xpi = bis[c * 512 + fp];
        float s = a * rm * rp;
        gv[r] = make_float2(s * (xmr * xpr + xmi * xpi), s * (xmr * xpi - xmi * xpr));
    }
    __syncthreads();
    #pragma unroll
    for (int r = 0; r < 16; r++) {
        int t = tid + r * NTHR;
        gs[(t >> 9) * 517 + (t & 511)] = gv[r];
    }
    __syncthreads();   // brs/bis dead -> A/B regions free
    if (tid == 0) {    // prefetch B chunks 0 and 1
        mbar_expect(mbB0, 12800);
        bulk_g2s(sbase + OFF_B, (const char*)g_bmb, 12800, mbB0);
        mbar_expect(mbB1, 12800);
        bulk_g2s(sbase + OFF_B + 12800, (const char*)g_bmb + 12800, 12800, mbB1);
    }

    const unsigned e = PAIR_TBL[lane];
    const int iCh = e & 255, jCh = (e >> 8) & 255;
    const bool dg = (e & 0x10000u) != 0;

    // ldmatrix per-lane address parts
    const int mt = w & 3, nh = w >> 2;
    const unsigned arow = (unsigned)((mt * 16 + (lane & 7) + 8 * ((lane >> 3) & 1)) * 80
                                     + (lane >> 4) * 16);
    const unsigned brow = (unsigned)(((nh * 40) + (lane & 7)) * 80 + ((lane >> 3) & 3) * 16);

    float d[5][4] = {{0.f}};

    #pragma unroll 1
    for (int ch = 0; ch < CHUNKS; ch++) {
        const int b = ch & 1;
        // produce A(ch): bf16 hi/lo, rows lane (u) and lane+32 (v), cols 4w..4w+3
        unsigned uh[4], ul[4], vh[4], vl[4];
        #pragma unroll
        for (int r = 0; r < 4; r++) {
            int f = ch * 32 + 4 * w + r;
            float2 gi = gs[iCh * 517 + f], gj = gs[jCh * 517 + f];
            float u, v;
            if (dg) { u = gi.x*gi.x + gi.y*gi.y;  v = gj.x*gj.x + gj.y*gj.y; }
            else    { u = gi.x*gj.x + gi.y*gj.y;  v = gi.y*gj.x - gi.x*gj.y; }
            uh[r] = f2bf(u); ul[r] = f2bf(u - bf2f(uh[r]));
            vh[r] = f2bf(v); vl[r] = f2bf(v - bf2f(vh[r]));
        }
        char* Ab = sm_ + OFF_A + b * 10240;
        *(uint2*)(Ab + lane * 80 + 8 * w)        = make_uint2(uh[0]|(uh[1]<<16), uh[2]|(uh[3]<<16));
        *(uint2*)(Ab + 5120 + lane * 80 + 8 * w) = make_uint2(ul[0]|(ul[1]<<16), ul[2]|(ul[3]<<16));
        *(uint2*)(Ab + 2560 + lane * 80 + 8 * w) = make_uint2(vh[0]|(vh[1]<<16), vh[2]|(vh[3]<<16));
        *(uint2*)(Ab + 7680 + lane * 80 + 8 * w) = make_uint2(vl[0]|(vl[1]<<16), vl[2]|(vl[3]<<16));
        __syncthreads();   // A(ch) visible; mma(ch-1) done by all warps

        if (tid == 0 && ch >= 1 && ch + 1 < CHUNKS) {
            unsigned mb = ((ch + 1) & 1) ? mbB1 : mbB0;
            mbar_expect(mb, 12800);
            bulk_g2s(sbase + OFF_B + ((ch + 1) & 1) * 12800,
                     (const char*)g_bmb + (size_t)(ch + 1) * 12800, 12800, mb);
        }
        mbar_wait(b ? mbB1 : mbB0, (ch >> 1) & 1);

        const unsigned Abs = sbase + OFF_A + b * 10240;
        const unsigned Bbs = sbase + OFF_B + b * 12800;
        unsigned ah0[4], ah1[4], al0[4], al1[4];
        ldsm4(ah0, Abs + arow);               // hi, k0-15
        ldsm4(ah1, Abs + arow + 32);          // hi, k16-31
        ldsm4(al0, Abs + 5120 + arow);        // lo, k0-15
        ldsm4(al1, Abs + 5120 + arow + 32);   // lo, k16-31
        #pragma unroll
        for (int j = 0; j < 5; j++) {
            unsigned bh[4], bl[4];
            ldsm4(bh, Bbs + brow + j * 640);          // hi: k0-7,8-15,16-23,24-31
            ldsm4(bl, Bbs + 6400 + brow + j * 640);   // lo
            mma16816(d[j], ah0, bh[0], bh[1]);   // hi*hi  k0-15
            mma16816(d[j], al0, bh[0], bh[1]);   // lo*hi
            mma16816(d[j], ah0, bl[0], bl[1]);   // hi*lo
            mma16816(d[j], ah1, bh[2], bh[3]);   // hi*hi  k16-31
            mma16816(d[j], al1, bh[2], bh[3]);
            mma16816(d[j], ah1, bl[2], bl[3]);
        }
    }

    // ---- stage D fragments to smem (gs region dead) ----
    float* stg = (float*)sm_;   // [64 rows][82 f32]
    {
        const int g = lane >> 2, tig = lane & 3;
        #pragma unroll
        for (int j = 0; j < 5; j++) {
            int col = nh * 40 + j * 8 + 2 * tig;
            int row = mt * 16 + g;
            *(float2*)(stg + row * 82 + col)       = make_float2(d[j][0], d[j][1]);
            *(float2*)(stg + (row + 8) * 82 + col) = make_float2(d[j][2], d[j][3]);
        }
    }
    __syncthreads();

    // ---- recombine into bc[c2][44] (B region; all mma done) ----
    float2* bc = (float2*)(sm_ + OFF_B);
    #pragma unroll
    for (int kk = 0; kk < 5; kk++) {
        int k = 5 * w + kk;
        float2 s13 = *(float2*)(stg + lane * 82 + 2 * k);          // (S1,S3)
        float2 s42 = *(float2*)(stg + (lane + 32) * 82 + 2 * k);   // (S4,S2)
        if (dg) {
            bc[(iCh * 9) * 44 + k] = s13;
            bc[(jCh * 9) * 44 + k] = s42;
        } else {
            bc[(iCh * 8 + jCh) * 44 + k] = make_float2(s13.x - s42.y, s13.y + s42.x);
            bc[(jCh * 8 + iCh) * 44 + k] = make_float2(s13.x + s42.y, s13.y - s42.x);
        }
    }
    __syncthreads();

    float* invd = (float*)(sm_ + OFF_A);
    if (tid < 40) {
        float s = 0.f;
        #pragma unroll
        for (int dd = 0; dd < 8; dd++) s += bc[(dd * 9) * 44 + tid].x;
        invd[tid] = 1.0f / fmaxf(s, 1e-20f);
    }
    float2* ct = (float2*)sm_;   // overlays stg (dead)
    #pragma unroll
    for (int r = 0; r < 16; r++) {
        int idx = tid + r * NTHR;
        ct[idx] = g_ct[idx];
    }
    __syncthreads();

    const unsigned long long* ctu = (const unsigned long long*)ct;
    const unsigned long long* bcu = (const unsigned long long*)bc;
    const int p  = tid & 63;
    const int kq = tid >> 6;
    unsigned long long acc[10] = {0,0,0,0,0,0,0,0,0,0};
    #pragma unroll 4
    for (int c = 0; c < 64; c++) {
        unsigned long long m = ctu[c * 64 + p];
        const unsigned long long* bp = bcu + c * 44 + 10 * kq;
        #pragma unroll
        for (int r = 0; r < 10; r++) fma2(acc[r], m, bp[r]);
    }
    float* zt = g_z + (size_t)tile * 2560;
    #pragma unroll
    for (int r = 0; r < 10; r++) {
        int k = 10 * kq + r;
        float lo, hi; unpack2(acc[r], lo, hi);
        zt[k * 64 + p] = (lo - hi) * invd[k];
    }
}

__global__ void __launch_bounds__(256) iir_pass1(const float* __restrict__ tau)
{
    int tid = blockIdx.x * 256 + threadIdx.x;
    int p = tid & 63, k = (tid >> 6) % 40, ch = (tid / 2560) & 15, b = tid / 40960;
    float a = tau[k], om = 1.0f - a;
    size_t base = ((size_t)b * 400 + ch * 25) * 2560 + k * 64 + p;
    float y = 0.f;
    #pragma unroll 5
    for (int i = 0; i < 25; i++)
        y = a * y + om * g_z[base + (size_t)i * 2560];
    g_cf[((b * 16 + ch) * 40 + k) * 64 + p] = y;
}

__global__ void __launch_bounds__(256) iir_pass2(const float* __restrict__ tau,
                                                 float* __restrict__ out)
{
    int tid = blockIdx.x * 256 + threadIdx.x;
    int p = tid & 63, k = (tid >> 6) % 40, ch = (tid / 2560) & 15, b = tid / 40960;
    float a = tau[k], om = 1.0f - a;
    float a2 = a * a, a4 = a2 * a2, a8 = a4 * a4, a16 = a8 * a8;
    float a25 = a16 * a8 * a;
    float cf[16];
    #pragma unroll
    for (int j = 0; j < 15; j++)
        cf[j] = (j < ch) ? g_cf[((b * 16 + j) * 40 + k) * 64 + p] : 0.f;
    float y = 0.f;
    #pragma unroll
    for (int j = 0; j < 15; j++)
        if (j < ch) y = cf[j] + a25 * y;
    size_t base = ((size_t)b * 400 + ch * 25) * 2560 + k * 64 + p;
    #pragma unroll 5
    for (int i = 0; i < 25; i++) {
        y = a * y + om * g_z[base + (size_t)i * 2560];
        out[base + (size_t)i * 2560] = y;
    }
}

extern "C" void kernel_launch(void* const* d_in, const int* in_sizes, int n_in,
                              void* d_out, int out_size)
{
    const float* br  = (const float*)d_in[0];
    const float* bi  = (const float*)d_in[1];
    const float* bmr = (const float*)d_in[2];
    const float* bmi = (const float*)d_in[3];
    const float* pr  = (const float*)d_in[4];
    const float* pi  = (const float*)d_in[5];
    const float* tau = (const float*)d_in[6];

    cudaFuncSetAttribute(pv_main, cudaFuncAttributeMaxDynamicSharedMemorySize, SMEM_TOTAL);

    prep<<<96, 256>>>(bmr, bmi, pr, pi);
    pv_main<<<TILES, NTHR, SMEM_TOTAL>>>(br, bi);
    iir_pass1<<<320, 256>>>(tau);
    iir_pass2<<<320, 256>>>(tau, (float*)d_out);
}